// round 13
// baseline (speedup 1.0000x reference)
#include <cuda_runtime.h>

// LearnableWaveletTransform: depthwise 1D cross-correlation, 2 shared 96-tap
// filters over x[64,128,4096] fp32, pad=48 -> out (l,h) each [64,128,4097].
//
// R13 = R10 (RPT=8, 5 blocks/SM, skew i+(i>>3), FFMA2 filter-pair packing)
// plus:
//  - DISTANCE-2 prefetch for weight pair and x refill (~24-issue slack vs
//    29-cyc LDS latency -> kills the per-kstep long-scoreboard stall that
//    capped fma at 56.7%).
//  - Single-pass staging of l+h in a separate smem buffer: 2 syncs (was 4),
//    no ordering hazard with the tail thread's sxs reads.

#define KW      96
#define PADW    48
#define TLEN    4096
#define TOUT    4097
#define NROWS   8192            // 64 * 128
#define NTHREADS 256
#define RPT     8
#define TILE    (NTHREADS * RPT)        // 2048
#define WINLEN  (TILE + KW)             // 2144
#define SKEWLEN (WINLEN + (WINLEN >> 3) + 4)  // +4 pad for distance-2 overrun
#define STGW    (TILE + (TILE >> 3) + 8)      // 2312, skewed staging width
#define HALFOFF ((long long)NROWS * (long long)TOUT)  // 33,562,624

typedef unsigned long long ull;

__device__ __forceinline__ ull ffma2(ull a, ull b, ull c) {
    ull d;
    asm("fma.rn.f32x2 %0, %1, %2, %3;" : "=l"(d) : "l"(a), "l"(b), "l"(c));
    return d;
}
__device__ __forceinline__ ull pack2(float lo, float hi) {
    ull r;
    asm("mov.b64 %0, {%1, %2};" : "=l"(r) : "f"(lo), "f"(hi));
    return r;
}
__device__ __forceinline__ void unpack2(ull v, float& lo, float& hi) {
    asm("mov.b64 {%0, %1}, %2;" : "=f"(lo), "=f"(hi) : "l"(v));
}

__global__ void __launch_bounds__(NTHREADS, 5)
wavelet_f32x2_r13(const float* __restrict__ x,
                  const float* __restrict__ hw,
                  const float* __restrict__ lw,
                  float* __restrict__ out)
{
    __shared__ float sxs[SKEWLEN];
    __shared__ ull wp[KW + 3];          // +3 pad: distance-2 prefetch overrun
    __shared__ float stg[2][STGW];      // staging for l (0) and h (1)

    const int row  = blockIdx.y;
    const int tile = blockIdx.x;
    const int tid  = threadIdx.x;
    const long long xbase = (long long)row * TLEN;
    const int t_base = tile * TILE;
    const int g0 = t_base - PADW;

    // Skewed window fill: sxs[i + (i>>3)] = x[row, g0 + i] (0-pad at edges)
    for (int i = tid; i < WINLEN; i += NTHREADS) {
        int g = g0 + i;
        sxs[i + (i >> 3)] = (g >= 0 && g < TLEN) ? x[xbase + g] : 0.0f;
    }
    if (tid < KW) wp[tid] = pack2(lw[tid], hw[tid]);   // lane.lo=l, lane.hi=h
    if (tid >= KW && tid < KW + 3) wp[tid] = 0ULL;
    if (tid < 4) sxs[SKEWLEN - 4 + tid] = 0.0f;        // pad area deterministic
    __syncthreads();

    // s0 = tid*8 -> phys(s0 + 8m + c) = 9*tid + 9m + c  (c < 8)
    const float* pbase = sxs + tid * 9;

    // Register window: xd holds x[s0+k .. s0+k+7] (duplicated pairs)
    ull xd[RPT];
    #pragma unroll
    for (int j = 0; j < RPT; ++j) {
        float v = pbase[j];
        xd[j] = pack2(v, v);
    }

    ull acc[RPT];
    #pragma unroll
    for (int j = 0; j < RPT; ++j) acc[j] = 0ULL;

    // Distance-2 pipelines.
    // Refill value for kstep k is x[s0+8+k], phys offset from pbase:
    //   9 + 9*(k/8) + (k%8). Weight for kstep k is wp[k].
    float xn0 = pbase[9];               // refill for kstep 0
    float xn1 = pbase[10];              // refill for kstep 1
    ull   wc  = wp[0];                  // weight for kstep 0
    ull   wn  = wp[1];                  // weight for kstep 1

    #pragma unroll 1
    for (int kk = 0; kk < KW; kk += RPT) {      // 12 outer chunks
        const float* pr = pbase + 9 + 9 * (kk >> 3);  // refill base, this chunk
        const ull*   pw = wp + kk;
        #pragma unroll
        for (int ki = 0; ki < RPT; ++ki) {
            // prefetch for kstep (kk+ki+2); offsets are compile-time per ki
            float xpf = pr[((ki + 2) >> 3) * 9 + ((ki + 2) & 7)];
            ull   wpf = pw[ki + 2];
            #pragma unroll
            for (int j = 0; j < RPT; ++j)
                acc[j] = ffma2(xd[j], wc, acc[j]);
            #pragma unroll
            for (int j = 0; j < RPT - 1; ++j) xd[j] = xd[j + 1];
            xd[RPT - 1] = pack2(xn0, xn0);
            xn0 = xn1;  xn1 = xpf;
            wc  = wn;   wn  = wpf;
        }
    }

    float lacc[RPT], hacc[RPT];
    #pragma unroll
    for (int j = 0; j < RPT; ++j) unpack2(acc[j], lacc[j], hacc[j]);

    // Tail output t = 4096: tile 1, window idx 2048..2143 (sxs is intact)
    float tl = 0.0f, th = 0.0f;
    if (tile == 1 && tid == NTHREADS - 1) {
        ull e = 0ULL;
        #pragma unroll 8
        for (int k = 0; k < KW; ++k) {
            int i = TILE + k;
            float v = sxs[i + (i >> 3)];
            e = ffma2(pack2(v, v), wp[k], e);
        }
        unpack2(e, tl, th);
    }

    // Single-pass staged, coalesced stores. phys(t) = t + (t>>3).
    #pragma unroll
    for (int j = 0; j < RPT; ++j) {
        stg[0][tid * 9 + j] = lacc[j];          // write: stride-9 lanes, CF
        stg[1][tid * 9 + j] = hacc[j];
    }
    __syncthreads();

    const long long obase = (long long)row * TOUT + t_base;
    #pragma unroll
    for (int j = 0; j < RPT; ++j) {
        int t = tid + j * NTHREADS;             // lane-consecutive reads + STG
        out[obase + t]           = stg[0][t + (t >> 3)];
        out[HALFOFF + obase + t] = stg[1][t + (t >> 3)];
    }

    if (tile == 1 && tid == NTHREADS - 1) {
        long long ob = (long long)row * TOUT;
        out[ob + TLEN]           = tl;
        out[HALFOFF + ob + TLEN] = th;
    }
}

extern "C" void kernel_launch(void* const* d_in, const int* in_sizes, int n_in,
                              void* d_out, int out_size) {
    // metadata order: x, h_w, l_w ; output: (l_outs, h_outs) concatenated
    const float* x  = (const float*)d_in[0];
    const float* hw = (const float*)d_in[1];
    const float* lw = (const float*)d_in[2];
    float* out = (float*)d_out;

    dim3 grid(2, NROWS);
    dim3 block(NTHREADS);
    wavelet_f32x2_r13<<<grid, block>>>(x, hw, lw, out);
}